// round 4
// baseline (speedup 1.0000x reference)
#include <cuda_runtime.h>

// Problem constants
#define NS 5
#define ND 64
#define NH 961
#define NV 1024
#define HPITCH 1092   // A copy: 63 zeros | 961 taps | 68 zeros (16B-aligned rows)
#define BPITCH 1088   // B copy: A shifted left by one float

// Precomputed once per launch:
__device__ float g_hp[NS][HPITCH];   // zero-padded taps
__device__ float g_sp[NS][NV];       // sp = conv_net(symbols), batch-independent

__device__ __forceinline__ float silu_f(float y) {
    return y * (1.0f / (1.0f + __expf(-y)));
}

__device__ __forceinline__ float warp_sum(float v) {
#pragma unroll
    for (int o = 16; o; o >>= 1) v += __shfl_xor_sync(0xffffffffu, v, o);
    return v;
}

// packed dual-FMA: acc(lo,hi) += x(lo,hi) * g(lo,hi), elementwise fp32
__device__ __forceinline__ void ffma2(unsigned long long& acc,
                                      unsigned long long x,
                                      unsigned long long g) {
    asm("fma.rn.f32x2 %0, %1, %2, %0;" : "+l"(acc) : "l"(x), "l"(g));
}
__device__ __forceinline__ float u64lo(unsigned long long u) {
    return __uint_as_float((unsigned)u);
}
__device__ __forceinline__ float u64hi(unsigned long long u) {
    return __uint_as_float((unsigned)(u >> 32));
}

// ---- round-3 conv kept for sp_kernel (cost negligible there) ----
__device__ __forceinline__ void conv4m(const float* __restrict__ g,
                                       const float* __restrict__ xs,
                                       float a[4]) {
    const ulonglong2* g2 = (const ulonglong2*)g;
    const ulonglong2* x2 = (const ulonglong2*)xs;
    unsigned long long A3 = 0ull, A1 = 0ull;
    float a2 = 0.f, a0 = 0.f;
    ulonglong2 G = g2[0];
#pragma unroll 4
    for (int m = 0; m < 16; m++) {
        const ulonglong2 Gn = g2[m + 1];
        const ulonglong2 X = x2[m];
        ffma2(A3, X.x, G.x);
        ffma2(A1, X.x, G.y);
        ffma2(A3, X.y, G.y);
        ffma2(A1, X.y, Gn.x);
        const float X0 = u64lo(X.x), X1 = u64hi(X.x);
        const float X2 = u64lo(X.y), X3 = u64hi(X.y);
        const float h1 = u64hi(G.x),  h2 = u64lo(G.y),  h3 = u64hi(G.y);
        const float h4 = u64lo(Gn.x), h5 = u64hi(Gn.x), h6 = u64lo(Gn.y);
        a2 = fmaf(X0, h1, a2); a2 = fmaf(X1, h2, a2);
        a2 = fmaf(X2, h3, a2); a2 = fmaf(X3, h4, a2);
        a0 = fmaf(X0, h3, a0); a0 = fmaf(X1, h4, a0);
        a0 = fmaf(X2, h5, a0); a0 = fmaf(X3, h6, a0);
        G = Gn;
    }
    a[3] = u64lo(A3) + u64hi(A3);
    a[1] = u64lo(A1) + u64hi(A1);
    a[2] = a2;
    a[0] = a0;
}

// --------------------------------------------------------------------------
// Kernel 1: pads h into g_hp AND computes sp. 5 blocks, one per s.
// --------------------------------------------------------------------------
__global__ __launch_bounds__(256) void sp_kernel(
    const float* __restrict__ h, const float* __restrict__ symbols,
    const float* __restrict__ gamma, const float* __restrict__ beta) {
    __shared__ __align__(16) float hp[HPITCH];
    __shared__ __align__(16) float xs[ND];
    __shared__ float wsum[8], wsq[8], mu_rs[2];
    const int s = blockIdx.x;
    const int t = threadIdx.x;
    const int warp = t >> 5, lane = t & 31;

    for (int i = t; i < HPITCH; i += 256) {
        const float v = (i >= 63 && i < 63 + NH) ? h[s * NH + (i - 63)] : 0.f;
        hp[i] = v;
        g_hp[s][i] = v;
    }
    if (t < ND) xs[t] = symbols[s * ND + t];
    __syncthreads();

    const int o0 = 4 * t;
    float a[4];
    conv4m(hp + (1020 - o0), xs, a);

    float sm = 0.f, sq = 0.f;
#pragma unroll
    for (int k = 0; k < 4; k++) {
        a[k] = silu_f(a[k]);
        sm += a[k];
        sq += a[k] * a[k];
    }
    sm = warp_sum(sm);
    sq = warp_sum(sq);
    if (lane == 0) { wsum[warp] = sm; wsq[warp] = sq; }
    __syncthreads();
    if (t == 0) {
        float s1 = 0.f, s2 = 0.f;
#pragma unroll
        for (int w = 0; w < 8; w++) { s1 += wsum[w]; s2 += wsq[w]; }
        const float mu = s1 * (1.f / NV);
        mu_rs[0] = mu;
        mu_rs[1] = rsqrtf(s2 * (1.f / NV) - mu * mu + 1e-3f);
    }
    __syncthreads();
    const float mu = mu_rs[0], rstd = mu_rs[1];
#pragma unroll
    for (int k = 0; k < 4; k++) {
        const int o = o0 + k;
        g_sp[s][o] = (a[k] - mu) * rstd * gamma[o] + beta[o];
    }
}

// --------------------------------------------------------------------------
// Kernel 2: fused per-batch pipeline. Block = 320 threads.
// Each thread computes 16 consecutive conv outputs of ONE s:
//   s = t/64, o0 = (t%64)*16.
// Conv is 100% packed f32x2: odd-k outputs read tap pairs from copy A,
// even-k outputs from copy B (A shifted by one float, built in SMEM).
// --------------------------------------------------------------------------
__global__ __launch_bounds__(320, 2) void main_kernel(
    const float* __restrict__ values,
    const float* __restrict__ gamma, const float* __restrict__ beta,
    float* __restrict__ out) {
    __shared__ __align__(16) float bufA[NS][HPITCH];   // taps; later aliased by vp[NS][NV]
    __shared__ __align__(16) float bufB[NS][BPITCH];   // taps shifted by 1 float
    __shared__ __align__(16) float xs[NS][ND];
    __shared__ float wsum[NS][2], wsq[NS][2];
    __shared__ float mu_s[NS], rs_s[NS];
    __shared__ int   spart[25][8];
    __shared__ float prob[NS][NS];

    const int b = blockIdx.x;
    const int t = threadIdx.x;
    const int warp = t >> 5, lane = t & 31;

    // ---- load padded taps (copy A) + this batch's x ----
    {
        const float4* src = (const float4*)(&g_hp[0][0]);
        float4* dst = (float4*)(&bufA[0][0]);
        for (int i = t; i < NS * HPITCH / 4; i += 320) dst[i] = src[i];
        const float4* v4 = (const float4*)(values + (size_t)b * (NS * ND));
        if (t < NS * ND / 4) ((float4*)(&xs[0][0]))[t] = v4[t];
    }
    __syncthreads();
    // ---- build copy B in SMEM: B[i] = A[i+1] ----
    for (int i = t; i < NS * (BPITCH / 4); i += 320) {
        const int s = i / (BPITCH / 4), q = i % (BPITCH / 4);
        const float4* A4 = (const float4*)(&bufA[s][0]);
        const float4 F = A4[q];
        const float4 F2 = A4[q + 1];   // q=271 reads zero-pad floats 1088..1091
        float4 r; r.x = F.y; r.y = F.z; r.z = F.w; r.w = F2.x;
        ((float4*)(&bufB[s][0]))[q] = r;
    }
    __syncthreads();

    // ---- conv: 16 outputs, fully packed ----
    const int s = t >> 6;
    const int o0 = (t & 63) << 4;
    const unsigned long long* aA =
        (const unsigned long long*)(&bufA[s][1008 - o0]);
    const unsigned long long* aB =
        (const unsigned long long*)(&bufB[s][1008 - o0]);
    const unsigned long long* xu = (const unsigned long long*)(&xs[s][0]);

    unsigned long long acc[16];
#pragma unroll
    for (int k = 0; k < 16; k++) acc[k] = 0ull;
    unsigned long long WA[8], WB[8];
#pragma unroll
    for (int i = 0; i < 8; i++) { WA[i] = aA[i]; WB[i] = aB[i]; }
#pragma unroll
    for (int st = 0; st < 32; st++) {       // d = 2*st
        const unsigned long long X = xu[st];    // (x_d, x_{d+1}) broadcast
#pragma unroll
        for (int j = 0; j < 8; j++) {
            ffma2(acc[2 * j + 1], X, WA[7 - j]);   // odd k from copy A
            ffma2(acc[2 * j],     X, WB[7 - j]);   // even k from copy B
        }
#pragma unroll
        for (int i = 0; i < 7; i++) { WA[i] = WA[i + 1]; WB[i] = WB[i + 1]; }
        WA[7] = aA[st + 8];
        WB[7] = aB[st + 8];
    }

    // ---- silu + LN stats ----
    float a[16];
    float sm = 0.f, sq = 0.f;
#pragma unroll
    for (int k = 0; k < 16; k++) {
        float v = u64lo(acc[k]) + u64hi(acc[k]);
        v = silu_f(v);
        a[k] = v;
        sm += v;
        sq += v * v;
    }
    sm = warp_sum(sm);
    sq = warp_sum(sq);
    if (lane == 0) { wsum[s][warp & 1] = sm; wsq[s][warp & 1] = sq; }
    __syncthreads();
    if (t < NS) {
        const float s1 = wsum[t][0] + wsum[t][1];
        const float s2 = wsq[t][0] + wsq[t][1];
        const float mu = s1 * (1.f / NV);
        mu_s[t] = mu;
        rs_s[t] = rsqrtf(s2 * (1.f / NV) - mu * mu + 1e-3f);
    }
    __syncthreads();

    // ---- layernorm, write vp into (dead) bufA region ----
    float* vp = &bufA[0][0];                  // vp[s*NV + o], 20.5KB <= 21.8KB
    {
        const float mu = mu_s[s], rstd = rs_s[s];
        const float4* g4 = (const float4*)(gamma + o0);
        const float4* b4 = (const float4*)(beta + o0);
#pragma unroll
        for (int q = 0; q < 4; q++) {
            const float4 gm = g4[q], bt = b4[q];
            float4 r;
            r.x = (a[4 * q + 0] - mu) * rstd * gm.x + bt.x;
            r.y = (a[4 * q + 1] - mu) * rstd * gm.y + bt.y;
            r.z = (a[4 * q + 2] - mu) * rstd * gm.z + bt.z;
            r.w = (a[4 * q + 3] - mu) * rstd * gm.w + bt.w;
            ((float4*)(vp + s * NV + o0))[q] = r;
        }
    }
    __syncthreads();

    // ---- scores: sign(vp_i)*sign(vp_i+sp_j) = 1 - 2*(signbit xor) ----
    float4 SP[NS];     // kept in regs through the epilogue
    float4 VPX[NS];
    if (t < 256) {
#pragma unroll
        for (int j = 0; j < NS; j++) SP[j] = ((const float4*)(&g_sp[j][0]))[t];
#pragma unroll
        for (int i = 0; i < NS; i++) VPX[i] = ((const float4*)(vp + i * NV))[t];

        int acc25[25];
#pragma unroll
        for (int p = 0; p < 25; p++) acc25[p] = 0;
#pragma unroll
        for (int j = 0; j < NS; j++) {
            const float spv[4] = {SP[j].x, SP[j].y, SP[j].z, SP[j].w};
#pragma unroll
            for (int i = 0; i < NS; i++) {
                const float vv[4] = {VPX[i].x, VPX[i].y, VPX[i].z, VPX[i].w};
                int acv = 0;
#pragma unroll
                for (int k = 0; k < 4; k++) {
                    const float c = vv[k] + spv[k];
                    acv += (int)((__float_as_uint(vv[k]) ^
                                  __float_as_uint(c)) >> 31);
                }
                acc25[j * NS + i] = acv;
            }
        }
#pragma unroll
        for (int p = 0; p < 25; p++) {
            const int v = __reduce_add_sync(0xffffffffu, acc25[p]);
            if (lane == 0) spart[p][warp] = v;
        }
    }
    __syncthreads();
    if (t < 25) {
        int smv = 0;
#pragma unroll
        for (int w = 0; w < 8; w++) smv += spart[t][w];
        ((float*)&spart[t][0])[0] = (float)(NV - 2 * smv) * (1.f / NV);
    }
    __syncthreads();
    if (t < NS) {
        float sc[NS], m = -1e30f;
#pragma unroll
        for (int i = 0; i < NS; i++) {
            sc[i] = ((float*)&spart[t * NS + i][0])[0];
            m = fmaxf(m, sc[i]);
        }
        float ssum = 0.f;
#pragma unroll
        for (int i = 0; i < NS; i++) { sc[i] = __expf(sc[i] - m); ssum += sc[i]; }
        const float inv = 1.f / ssum;
#pragma unroll
        for (int i = 0; i < NS; i++) prob[t][i] = sc[i] * inv;
    }
    __syncthreads();

    // ---- att = prob @ vp (vp cols still in regs) ; out = silu(att*sp) ----
    if (t < 256) {
        float4* out4 = (float4*)(out + (size_t)b * (NS * NV));
#pragma unroll
        for (int j = 0; j < NS; j++) {
            const float p0 = prob[j][0], p1 = prob[j][1], p2 = prob[j][2],
                        p3 = prob[j][3], p4 = prob[j][4];
            const float spv[4] = {SP[j].x, SP[j].y, SP[j].z, SP[j].w};
            float r[4];
#pragma unroll
            for (int k = 0; k < 4; k++) {
                const float v0 = (k == 0) ? VPX[0].x : (k == 1) ? VPX[0].y
                                : (k == 2) ? VPX[0].z : VPX[0].w;
                const float v1 = (k == 0) ? VPX[1].x : (k == 1) ? VPX[1].y
                                : (k == 2) ? VPX[1].z : VPX[1].w;
                const float v2 = (k == 0) ? VPX[2].x : (k == 1) ? VPX[2].y
                                : (k == 2) ? VPX[2].z : VPX[2].w;
                const float v3 = (k == 0) ? VPX[3].x : (k == 1) ? VPX[3].y
                                : (k == 2) ? VPX[3].z : VPX[3].w;
                const float v4 = (k == 0) ? VPX[4].x : (k == 1) ? VPX[4].y
                                : (k == 2) ? VPX[4].z : VPX[4].w;
                const float atv = p0 * v0 + p1 * v1 + p2 * v2 + p3 * v3 + p4 * v4;
                r[k] = silu_f(atv * spv[k]);
            }
            float4 w4;
            w4.x = r[0]; w4.y = r[1]; w4.z = r[2]; w4.w = r[3];
            out4[j * 256 + t] = w4;
        }
    }
}

extern "C" void kernel_launch(void* const* d_in, const int* in_sizes, int n_in,
                              void* d_out, int out_size) {
    const float* values  = (const float*)d_in[0];
    const float* h       = (const float*)d_in[1];
    const float* symbols = (const float*)d_in[2];
    const float* gamma   = (const float*)d_in[3];
    const float* beta    = (const float*)d_in[4];
    float* out = (float*)d_out;

    const int B = in_sizes[0] / (NS * ND);

    sp_kernel<<<NS, 256>>>(h, symbols, gamma, beta);
    main_kernel<<<B, 320>>>(values, gamma, beta, out);
}

// round 5
// speedup vs baseline: 1.3520x; 1.3520x over previous
#include <cuda_runtime.h>

// Problem constants
#define NS 5
#define ND 64
#define NV 1024
#define NH 961
#define HPITCH 1092   // A copy: 63 zeros | 961 taps | 68 zeros (16B-aligned rows)
#define BPITCH 1088   // B copy: A shifted left by one float

// Precomputed once per launch:
__device__ float g_hp[NS][HPITCH];   // zero-padded taps
__device__ float g_hb[NS][BPITCH];   // taps shifted by one float: g_hb[i] = g_hp[i+1]
__device__ float g_sp[NS][NV];       // sp = conv_net(symbols), batch-independent

__device__ __forceinline__ float silu_f(float y) {
    return y * (1.0f / (1.0f + __expf(-y)));
}

__device__ __forceinline__ float warp_sum(float v) {
#pragma unroll
    for (int o = 16; o; o >>= 1) v += __shfl_xor_sync(0xffffffffu, v, o);
    return v;
}

// packed dual-FMA: acc(lo,hi) += x(lo,hi) * g(lo,hi), elementwise fp32
__device__ __forceinline__ void ffma2(unsigned long long& acc,
                                      unsigned long long x,
                                      unsigned long long g) {
    asm("fma.rn.f32x2 %0, %1, %2, %0;" : "+l"(acc) : "l"(x), "l"(g));
}
__device__ __forceinline__ float u64lo(unsigned long long u) {
    return __uint_as_float((unsigned)u);
}
__device__ __forceinline__ float u64hi(unsigned long long u) {
    return __uint_as_float((unsigned)(u >> 32));
}

// a[k] = sum_{d=0..63} xs[d] * gA[d + 3 - k]  (k = 0..3)
// gA 16B-aligned; gB[i] == gA[i+1] (also 16B-aligned).
// 100% packed: even-start tap pairs (k=3,1) from copy A, odd-start (k=2,0)
// from copy B. 8 ffma2 + 3 LDS.128 per 4 d-steps. Lane stride is 16B with
// 16B loads -> perfectly tiles all 32 banks (conflict-free).
__device__ __forceinline__ void conv4p(const float* __restrict__ gA,
                                       const float* __restrict__ gB,
                                       const float* __restrict__ xs,
                                       float a[4]) {
    const ulonglong2* a2v = (const ulonglong2*)gA;
    const ulonglong2* b2v = (const ulonglong2*)gB;
    const ulonglong2* x2v = (const ulonglong2*)xs;
    unsigned long long A3 = 0ull, A2 = 0ull, A1 = 0ull, A0 = 0ull;
    ulonglong2 GA = a2v[0];
    ulonglong2 GB = b2v[0];
#pragma unroll
    for (int m = 0; m < 16; m++) {
        const ulonglong2 GAn = a2v[m + 1];
        const ulonglong2 GBn = b2v[m + 1];
        const ulonglong2 X = x2v[m];
        // d-pair (4m, 4m+1)
        ffma2(A3, X.x, GA.x);    // taps g[4m],g[4m+1]
        ffma2(A1, X.x, GA.y);    // g[4m+2],g[4m+3]
        ffma2(A2, X.x, GB.x);    // g[4m+1],g[4m+2]
        ffma2(A0, X.x, GB.y);    // g[4m+3],g[4m+4]
        // d-pair (4m+2, 4m+3)
        ffma2(A3, X.y, GA.y);    // g[4m+2],g[4m+3]
        ffma2(A1, X.y, GAn.x);   // g[4m+4],g[4m+5]
        ffma2(A2, X.y, GB.y);    // g[4m+3],g[4m+4]
        ffma2(A0, X.y, GBn.x);   // g[4m+5],g[4m+6]
        GA = GAn;
        GB = GBn;
    }
    a[3] = u64lo(A3) + u64hi(A3);
    a[2] = u64lo(A2) + u64hi(A2);
    a[1] = u64lo(A1) + u64hi(A1);
    a[0] = u64lo(A0) + u64hi(A0);
}

// --------------------------------------------------------------------------
// Kernel 1: pads h into g_hp + g_hb AND computes sp. 5 blocks, one per s.
// --------------------------------------------------------------------------
__global__ __launch_bounds__(256) void sp_kernel(
    const float* __restrict__ h, const float* __restrict__ symbols,
    const float* __restrict__ gamma, const float* __restrict__ beta) {
    __shared__ __align__(16) float hpA[HPITCH];
    __shared__ __align__(16) float hpB[BPITCH];
    __shared__ __align__(16) float xs[ND];
    __shared__ float wsum[8], wsq[8], mu_rs[2];
    const int s = blockIdx.x;
    const int t = threadIdx.x;
    const int warp = t >> 5, lane = t & 31;

    for (int i = t; i < HPITCH; i += 256) {
        const float v = (i >= 63 && i < 63 + NH) ? h[s * NH + (i - 63)] : 0.f;
        hpA[i] = v;
        g_hp[s][i] = v;
    }
    for (int i = t; i < BPITCH; i += 256) {
        const int j = i + 1;
        const float v = (j >= 63 && j < 63 + NH) ? h[s * NH + (j - 63)] : 0.f;
        hpB[i] = v;
        g_hb[s][i] = v;
    }
    if (t < ND) xs[t] = symbols[s * ND + t];
    __syncthreads();

    const int o0 = 4 * t;
    float a[4];
    conv4p(hpA + (1020 - o0), hpB + (1020 - o0), xs, a);

    float sm = 0.f, sq = 0.f;
#pragma unroll
    for (int k = 0; k < 4; k++) {
        a[k] = silu_f(a[k]);
        sm += a[k];
        sq += a[k] * a[k];
    }
    sm = warp_sum(sm);
    sq = warp_sum(sq);
    if (lane == 0) { wsum[warp] = sm; wsq[warp] = sq; }
    __syncthreads();
    if (t == 0) {
        float s1 = 0.f, s2 = 0.f;
#pragma unroll
        for (int w = 0; w < 8; w++) { s1 += wsum[w]; s2 += wsq[w]; }
        const float mu = s1 * (1.f / NV);
        mu_rs[0] = mu;
        mu_rs[1] = rsqrtf(s2 * (1.f / NV) - mu * mu + 1e-3f);
    }
    __syncthreads();
    const float mu = mu_rs[0], rstd = mu_rs[1];
#pragma unroll
    for (int k = 0; k < 4; k++) {
        const int o = o0 + k;
        g_sp[s][o] = (a[k] - mu) * rstd * gamma[o] + beta[o];
    }
}

// --------------------------------------------------------------------------
// Kernel 2: fused per-batch pipeline (round-3 structure + full pairing).
// One CTA / batch element; 256 threads; each thread owns columns 4t..4t+3
// of all 5 sequence positions -> vp never leaves registers.
// --------------------------------------------------------------------------
__global__ __launch_bounds__(256, 4) void main_kernel(
    const float* __restrict__ values,
    const float* __restrict__ gamma, const float* __restrict__ beta,
    float* __restrict__ out) {
    __shared__ __align__(16) float hpA[NS][HPITCH];   // 21840 B
    __shared__ __align__(16) float hpB[NS][BPITCH];   // 21760 B
    __shared__ __align__(16) float xs[NS][ND];        //  1280 B
    __shared__ float wsum[NS][8], wsq[NS][8];
    __shared__ float mu_s[NS], rs_s[NS];
    __shared__ int   spart[25][8];
    __shared__ float prob[NS][NS];

    const int b = blockIdx.x;
    const int t = threadIdx.x;
    const int warp = t >> 5, lane = t & 31;
    const int o0 = 4 * t;

    {   // copy both tap copies + this batch's x into smem (all float4)
        const float4* srcA = (const float4*)(&g_hp[0][0]);
        float4* dstA = (float4*)(&hpA[0][0]);
        for (int i = t; i < NS * HPITCH / 4; i += 256) dstA[i] = srcA[i];
        const float4* srcB = (const float4*)(&g_hb[0][0]);
        float4* dstB = (float4*)(&hpB[0][0]);
        for (int i = t; i < NS * BPITCH / 4; i += 256) dstB[i] = srcB[i];
        const float4* v4 = (const float4*)(values + (size_t)b * (NS * ND));
        if (t < NS * ND / 4) ((float4*)(&xs[0][0]))[t] = v4[t];
    }
    __syncthreads();

    // ---- conv + silu ----
    float vpreg[NS][4];
#pragma unroll
    for (int s = 0; s < NS; s++) {
        float a[4];
        conv4p(&hpA[s][1020 - o0], &hpB[s][1020 - o0], xs[s], a);
        float sm = 0.f, sq = 0.f;
#pragma unroll
        for (int k = 0; k < 4; k++) {
            const float v = silu_f(a[k]);
            vpreg[s][k] = v;
            sm += v;
            sq += v * v;
        }
        sm = warp_sum(sm);
        sq = warp_sum(sq);
        if (lane == 0) { wsum[s][warp] = sm; wsq[s][warp] = sq; }
    }
    __syncthreads();
    if (t < NS) {
        float s1 = 0.f, s2 = 0.f;
#pragma unroll
        for (int w = 0; w < 8; w++) { s1 += wsum[t][w]; s2 += wsq[t][w]; }
        const float mu = s1 * (1.f / NV);
        mu_s[t] = mu;
        rs_s[t] = rsqrtf(s2 * (1.f / NV) - mu * mu + 1e-3f);
    }
    __syncthreads();

    // ---- layernorm in registers ----
    const float4 gm4 = ((const float4*)gamma)[t];
    const float4 bt4 = ((const float4*)beta)[t];
    const float gmk[4] = {gm4.x, gm4.y, gm4.z, gm4.w};
    const float btk[4] = {bt4.x, bt4.y, bt4.z, bt4.w};
#pragma unroll
    for (int s = 0; s < NS; s++) {
        const float mu = mu_s[s], rstd = rs_s[s];
#pragma unroll
        for (int k = 0; k < 4; k++)
            vpreg[s][k] = (vpreg[s][k] - mu) * rstd * gmk[k] + btk[k];
    }

    // ---- scores[j][i] = mean_v sign(vp_i) * sign(vp_i + sp_j) ----
    // sign(x)sign(x+sp) = 1 - 2*(signbit(x) ^ signbit(x+sp)); count flips.
    float4 SP[NS];
#pragma unroll
    for (int j = 0; j < NS; j++) SP[j] = ((const float4*)(&g_sp[j][0]))[t];

    unsigned uv[NS][4];
#pragma unroll
    for (int i = 0; i < NS; i++)
#pragma unroll
        for (int k = 0; k < 4; k++) uv[i][k] = __float_as_uint(vpreg[i][k]);

    int acc[25];
#pragma unroll
    for (int p = 0; p < 25; p++) acc[p] = 0;
#pragma unroll
    for (int j = 0; j < NS; j++) {
        const float spv[4] = {SP[j].x, SP[j].y, SP[j].z, SP[j].w};
#pragma unroll
        for (int i = 0; i < NS; i++) {
            int a = 0;
#pragma unroll
            for (int k = 0; k < 4; k++) {
                const float c = vpreg[i][k] + spv[k];
                a += (int)((uv[i][k] ^ __float_as_uint(c)) >> 31);
            }
            acc[j * NS + i] = a;
        }
    }
#pragma unroll
    for (int p = 0; p < 25; p++) {
        const int v = __reduce_add_sync(0xffffffffu, acc[p]);
        if (lane == 0) spart[p][warp] = v;
    }
    __syncthreads();
    if (t < 25) {
        int sm = 0;
#pragma unroll
        for (int w = 0; w < 8; w++) sm += spart[t][w];
        ((float*)&spart[t][0])[0] = (float)(NV - 2 * sm) * (1.f / NV);
    }
    __syncthreads();
    if (t < NS) {
        float sc[NS], m = -1e30f;
#pragma unroll
        for (int i = 0; i < NS; i++) {
            sc[i] = ((float*)&spart[t * NS + i][0])[0];
            m = fmaxf(m, sc[i]);
        }
        float ssum = 0.f;
#pragma unroll
        for (int i = 0; i < NS; i++) { sc[i] = __expf(sc[i] - m); ssum += sc[i]; }
        const float inv = 1.f / ssum;
#pragma unroll
        for (int i = 0; i < NS; i++) prob[t][i] = sc[i] * inv;
    }
    __syncthreads();

    // ---- att = prob @ vp (registers) ; out = silu(att * sp) ----
    float4* out4 = (float4*)(out + (size_t)b * (NS * NV));
#pragma unroll
    for (int j = 0; j < NS; j++) {
        const float p0 = prob[j][0], p1 = prob[j][1], p2 = prob[j][2],
                    p3 = prob[j][3], p4 = prob[j][4];
        const float spv[4] = {SP[j].x, SP[j].y, SP[j].z, SP[j].w};
        float r[4];
#pragma unroll
        for (int k = 0; k < 4; k++) {
            const float atv = p0 * vpreg[0][k] + p1 * vpreg[1][k] +
                              p2 * vpreg[2][k] + p3 * vpreg[3][k] +
                              p4 * vpreg[4][k];
            r[k] = silu_f(atv * spv[k]);
        }
        float4 v4;
        v4.x = r[0]; v4.y = r[1]; v4.z = r[2]; v4.w = r[3];
        out4[j * 256 + t] = v4;
    }
}

extern "C" void kernel_launch(void* const* d_in, const int* in_sizes, int n_in,
                              void* d_out, int out_size) {
    const float* values  = (const float*)d_in[0];
    const float* h       = (const float*)d_in[1];
    const float* symbols = (const float*)d_in[2];
    const float* gamma   = (const float*)d_in[3];
    const float* beta    = (const float*)d_in[4];
    float* out = (float*)d_out;

    const int B = in_sizes[0] / (NS * ND);

    sp_kernel<<<NS, 256>>>(h, symbols, gamma, beta);
    main_kernel<<<B, 256>>>(values, gamma, beta, out);
}

// round 6
// speedup vs baseline: 1.5307x; 1.1322x over previous
#include <cuda_runtime.h>

// Problem constants
#define NS 5
#define ND 64
#define NV 1024
#define NH 961
#define HPITCH 1092   // A copy: 63 zeros | 961 taps | 68 zeros (16B-aligned rows)
#define BPITCH 1088   // B copy: A shifted left by one float

// Precomputed once per launch:
__device__ float g_hp[NS][HPITCH];   // zero-padded taps
__device__ float g_hb[NS][BPITCH];   // g_hb[i] = g_hp[i+1]
__device__ float g_sp[NS][NV];       // sp = conv_net(symbols), batch-independent

__device__ __forceinline__ float silu_f(float y) {
    return y * (1.0f / (1.0f + __expf(-y)));
}

__device__ __forceinline__ float warp_sum(float v) {
#pragma unroll
    for (int o = 16; o; o >>= 1) v += __shfl_xor_sync(0xffffffffu, v, o);
    return v;
}

// packed dual-FMA: acc(lo,hi) += x(lo,hi) * g(lo,hi), elementwise fp32
__device__ __forceinline__ void ffma2(unsigned long long& acc,
                                      unsigned long long x,
                                      unsigned long long g) {
    asm("fma.rn.f32x2 %0, %1, %2, %0;" : "+l"(acc) : "l"(x), "l"(g));
}
__device__ __forceinline__ float u64lo(unsigned long long u) {
    return __uint_as_float((unsigned)u);
}
__device__ __forceinline__ float u64hi(unsigned long long u) {
    return __uint_as_float((unsigned)(u >> 32));
}

// ---- single-batch fully packed conv (used by sp_kernel only) ----
__device__ __forceinline__ void conv4p(const float* __restrict__ gA,
                                       const float* __restrict__ gB,
                                       const float* __restrict__ xs,
                                       float a[4]) {
    const ulonglong2* a2v = (const ulonglong2*)gA;
    const ulonglong2* b2v = (const ulonglong2*)gB;
    const ulonglong2* x2v = (const ulonglong2*)xs;
    unsigned long long A3 = 0ull, A2 = 0ull, A1 = 0ull, A0 = 0ull;
    ulonglong2 GA = a2v[0];
    ulonglong2 GB = b2v[0];
#pragma unroll
    for (int m = 0; m < 16; m++) {
        const ulonglong2 GAn = a2v[m + 1];
        const ulonglong2 GBn = b2v[m + 1];
        const ulonglong2 X = x2v[m];
        ffma2(A3, X.x, GA.x);
        ffma2(A1, X.x, GA.y);
        ffma2(A2, X.x, GB.x);
        ffma2(A0, X.x, GB.y);
        ffma2(A3, X.y, GA.y);
        ffma2(A1, X.y, GAn.x);
        ffma2(A2, X.y, GB.y);
        ffma2(A0, X.y, GBn.x);
        GA = GAn;
        GB = GBn;
    }
    a[3] = u64lo(A3) + u64hi(A3);
    a[2] = u64lo(A2) + u64hi(A2);
    a[1] = u64lo(A1) + u64hi(A1);
    a[0] = u64lo(A0) + u64hi(A0);
}

// --------------------------------------------------------------------------
// Kernel 1: pads h into g_hp + g_hb AND computes sp. 5 blocks, one per s.
// --------------------------------------------------------------------------
__global__ __launch_bounds__(256) void sp_kernel(
    const float* __restrict__ h, const float* __restrict__ symbols,
    const float* __restrict__ gamma, const float* __restrict__ beta) {
    __shared__ __align__(16) float hpA[HPITCH];
    __shared__ __align__(16) float hpB[BPITCH];
    __shared__ __align__(16) float xs[ND];
    __shared__ float wsum[8], wsq[8], mu_rs[2];
    const int s = blockIdx.x;
    const int t = threadIdx.x;
    const int warp = t >> 5, lane = t & 31;

    for (int i = t; i < HPITCH; i += 256) {
        const float v = (i >= 63 && i < 63 + NH) ? h[s * NH + (i - 63)] : 0.f;
        hpA[i] = v;
        g_hp[s][i] = v;
    }
    for (int i = t; i < BPITCH; i += 256) {
        const int j = i + 1;
        const float v = (j >= 63 && j < 63 + NH) ? h[s * NH + (j - 63)] : 0.f;
        hpB[i] = v;
        g_hb[s][i] = v;
    }
    if (t < ND) xs[t] = symbols[s * ND + t];
    __syncthreads();

    const int o0 = 4 * t;
    float a[4];
    conv4p(hpA + (1020 - o0), hpB + (1020 - o0), xs, a);

    float sm = 0.f, sq = 0.f;
#pragma unroll
    for (int k = 0; k < 4; k++) {
        a[k] = silu_f(a[k]);
        sm += a[k];
        sq += a[k] * a[k];
    }
    sm = warp_sum(sm);
    sq = warp_sum(sq);
    if (lane == 0) { wsum[warp] = sm; wsq[warp] = sq; }
    __syncthreads();
    if (t == 0) {
        float s1 = 0.f, s2 = 0.f;
#pragma unroll
        for (int w = 0; w < 8; w++) { s1 += wsum[w]; s2 += wsq[w]; }
        const float mu = s1 * (1.f / NV);
        mu_rs[0] = mu;
        mu_rs[1] = rsqrtf(s2 * (1.f / NV) - mu * mu + 1e-3f);
    }
    __syncthreads();
    const float mu = mu_rs[0], rstd = mu_rs[1];
#pragma unroll
    for (int k = 0; k < 4; k++) {
        const int o = o0 + k;
        g_sp[s][o] = (a[k] - mu) * rstd * gamma[o] + beta[o];
    }
}

// --------------------------------------------------------------------------
// Kernel 2: fused pipeline, TWO batches per CTA.
// Batch loop innermost in the conv -> window LDS amortized over 2 batches,
// 100% packed f32x2 MACs. Batch-0 vp lives in registers; batch-1 vp is
// written to the dead tap region of SMEM (each thread re-reads only its own
// columns, so no extra synchronization is needed).
// --------------------------------------------------------------------------
__global__ __launch_bounds__(256, 3) void main_kernel(
    const float* __restrict__ values,
    const float* __restrict__ gamma, const float* __restrict__ beta,
    float* __restrict__ out, int B) {
    __shared__ __align__(16) float hpA[NS][HPITCH];   // 21840 B (aliased by vp1 later)
    __shared__ __align__(16) float hpB[NS][BPITCH];   // 21760 B
    __shared__ __align__(16) float xs[2][NS][ND];     //  5120 B... (2560 B)
    __shared__ float wsum[2][NS][8], wsq[2][NS][8];
    __shared__ float mu_s[2][NS], rs_s[2][NS];
    __shared__ int   spart[25][8];
    __shared__ float prob[NS][NS];

    const int b0 = 2 * blockIdx.x;
    const int b1 = b0 + 1;
    const int t = threadIdx.x;
    const int warp = t >> 5, lane = t & 31;
    const int o0 = 4 * t;

    {   // taps + both batches' x (contiguous: b1 = b0+1)
        const float4* srcA = (const float4*)(&g_hp[0][0]);
        float4* dstA = (float4*)(&hpA[0][0]);
        for (int i = t; i < NS * HPITCH / 4; i += 256) dstA[i] = srcA[i];
        const float4* srcB = (const float4*)(&g_hb[0][0]);
        float4* dstB = (float4*)(&hpB[0][0]);
        for (int i = t; i < NS * BPITCH / 4; i += 256) dstB[i] = srcB[i];
        const float4* v4 = (const float4*)(values + (size_t)b0 * (NS * ND));
        const int nfl = (b1 < B) ? (2 * NS * ND / 4) : (NS * ND / 4);
        if (t < nfl) ((float4*)(&xs[0][0][0]))[t] = v4[t];
        else if (t < 2 * NS * ND / 4)
            ((float4*)(&xs[0][0][0]))[t] = make_float4(0.f, 0.f, 0.f, 0.f);
    }
    __syncthreads();

    // ---- conv (batch-innermost) + silu + LN partial sums ----
    float sil[2][NS][4];
#pragma unroll
    for (int s = 0; s < NS; s++) {
        const ulonglong2* a2v = (const ulonglong2*)(&hpA[s][1020 - o0]);
        const ulonglong2* b2v = (const ulonglong2*)(&hpB[s][1020 - o0]);
        const ulonglong2* x0 = (const ulonglong2*)(&xs[0][s][0]);
        const ulonglong2* x1 = (const ulonglong2*)(&xs[1][s][0]);
        unsigned long long P3 = 0ull, P2 = 0ull, P1 = 0ull, P0 = 0ull;
        unsigned long long Q3 = 0ull, Q2 = 0ull, Q1 = 0ull, Q0 = 0ull;
        ulonglong2 GA = a2v[0];
        ulonglong2 GB = b2v[0];
#pragma unroll
        for (int m = 0; m < 16; m++) {
            const ulonglong2 GAn = a2v[m + 1];
            const ulonglong2 GBn = b2v[m + 1];
            const ulonglong2 X = x0[m];
            const ulonglong2 Y = x1[m];
            ffma2(P3, X.x, GA.x);  ffma2(P1, X.x, GA.y);
            ffma2(P2, X.x, GB.x);  ffma2(P0, X.x, GB.y);
            ffma2(P3, X.y, GA.y);  ffma2(P1, X.y, GAn.x);
            ffma2(P2, X.y, GB.y);  ffma2(P0, X.y, GBn.x);
            ffma2(Q3, Y.x, GA.x);  ffma2(Q1, Y.x, GA.y);
            ffma2(Q2, Y.x, GB.x);  ffma2(Q0, Y.x, GB.y);
            ffma2(Q3, Y.y, GA.y);  ffma2(Q1, Y.y, GAn.x);
            ffma2(Q2, Y.y, GB.y);  ffma2(Q0, Y.y, GBn.x);
            GA = GAn;
            GB = GBn;
        }
        float a0[4], a1[4];
        a0[3] = u64lo(P3) + u64hi(P3); a0[2] = u64lo(P2) + u64hi(P2);
        a0[1] = u64lo(P1) + u64hi(P1); a0[0] = u64lo(P0) + u64hi(P0);
        a1[3] = u64lo(Q3) + u64hi(Q3); a1[2] = u64lo(Q2) + u64hi(Q2);
        a1[1] = u64lo(Q1) + u64hi(Q1); a1[0] = u64lo(Q0) + u64hi(Q0);

        float sm0 = 0.f, sq0 = 0.f, sm1 = 0.f, sq1 = 0.f;
#pragma unroll
        for (int k = 0; k < 4; k++) {
            const float v0 = silu_f(a0[k]);
            sil[0][s][k] = v0; sm0 += v0; sq0 += v0 * v0;
            const float v1 = silu_f(a1[k]);
            sil[1][s][k] = v1; sm1 += v1; sq1 += v1 * v1;
        }
        sm0 = warp_sum(sm0); sq0 = warp_sum(sq0);
        sm1 = warp_sum(sm1); sq1 = warp_sum(sq1);
        if (lane == 0) {
            wsum[0][s][warp] = sm0; wsq[0][s][warp] = sq0;
            wsum[1][s][warp] = sm1; wsq[1][s][warp] = sq1;
        }
    }
    __syncthreads();
    if (t < 10) {
        const int bb = t / NS, ss = t % NS;
        float s1 = 0.f, s2 = 0.f;
#pragma unroll
        for (int w = 0; w < 8; w++) { s1 += wsum[bb][ss][w]; s2 += wsq[bb][ss][w]; }
        const float mu = s1 * (1.f / NV);
        mu_s[bb][ss] = mu;
        rs_s[bb][ss] = rsqrtf(s2 * (1.f / NV) - mu * mu + 1e-3f);
    }
    __syncthreads();

    // ---- layernorm: batch0 -> registers, batch1 -> SMEM alias over hpA ----
    float* vp1 = &hpA[0][0];               // flat [NS][NV], 20.5 KB <= 21.8 KB
    const float4 gm4 = ((const float4*)gamma)[t];
    const float4 bt4 = ((const float4*)beta)[t];
    const float gmk[4] = {gm4.x, gm4.y, gm4.z, gm4.w};
    const float btk[4] = {bt4.x, bt4.y, bt4.z, bt4.w};
    float vp0[NS][4];
#pragma unroll
    for (int s = 0; s < NS; s++) {
        const float mu0 = mu_s[0][s], rs0 = rs_s[0][s];
        const float mu1 = mu_s[1][s], rs1 = rs_s[1][s];
        float4 r;
        float* rr = (float*)&r;
#pragma unroll
        for (int k = 0; k < 4; k++) {
            vp0[s][k] = (sil[0][s][k] - mu0) * rs0 * gmk[k] + btk[k];
            rr[k]     = (sil[1][s][k] - mu1) * rs1 * gmk[k] + btk[k];
        }
        ((float4*)(vp1 + s * NV + o0))[0] = r;
    }

    // ---- epilogue, per batch sequentially ----
    float4 SP[NS];
#pragma unroll
    for (int j = 0; j < NS; j++) SP[j] = ((const float4*)(&g_sp[j][0]))[t];

#pragma unroll
    for (int bb = 0; bb < 2; bb++) {
        if (bb == 1 && b1 >= B) break;

        float4 VPX[NS];
        if (bb == 0) {
#pragma unroll
            for (int i = 0; i < NS; i++)
                VPX[i] = make_float4(vp0[i][0], vp0[i][1], vp0[i][2], vp0[i][3]);
        } else {
#pragma unroll
            for (int i = 0; i < NS; i++)
                VPX[i] = ((const float4*)(vp1 + i * NV))[t];
        }

        // scores: sign(v)*sign(v+sp) = 1 - 2*(signbit xor); count flips.
        int acc25[25];
#pragma unroll
        for (int p = 0; p < 25; p++) acc25[p] = 0;
#pragma unroll
        for (int j = 0; j < NS; j++) {
            const float spv[4] = {SP[j].x, SP[j].y, SP[j].z, SP[j].w};
#pragma unroll
            for (int i = 0; i < NS; i++) {
                const float vv[4] = {VPX[i].x, VPX[i].y, VPX[i].z, VPX[i].w};
                int a = 0;
#pragma unroll
                for (int k = 0; k < 4; k++) {
                    const float c = vv[k] + spv[k];
                    a += (int)((__float_as_uint(vv[k]) ^
                                __float_as_uint(c)) >> 31);
                }
                acc25[j * NS + i] = a;
            }
        }
#pragma unroll
        for (int p = 0; p < 25; p++) {
            const int v = __reduce_add_sync(0xffffffffu, acc25[p]);
            if (lane == 0) spart[p][warp] = v;
        }
        __syncthreads();
        if (t < 25) {
            int sm = 0;
#pragma unroll
            for (int w = 0; w < 8; w++) sm += spart[t][w];
            ((float*)&spart[t][0])[0] = (float)(NV - 2 * sm) * (1.f / NV);
        }
        __syncthreads();
        if (t < NS) {
            float sc[NS], m = -1e30f;
#pragma unroll
            for (int i = 0; i < NS; i++) {
                sc[i] = ((float*)&spart[t * NS + i][0])[0];
                m = fmaxf(m, sc[i]);
            }
            float ssum = 0.f;
#pragma unroll
            for (int i = 0; i < NS; i++) { sc[i] = __expf(sc[i] - m); ssum += sc[i]; }
            const float inv = 1.f / ssum;
#pragma unroll
            for (int i = 0; i < NS; i++) prob[t][i] = sc[i] * inv;
        }
        __syncthreads();

        float4* out4 = (float4*)(out + (size_t)(b0 + bb) * (NS * NV));
#pragma unroll
        for (int j = 0; j < NS; j++) {
            const float p0 = prob[j][0], p1 = prob[j][1], p2 = prob[j][2],
                        p3 = prob[j][3], p4 = prob[j][4];
            const float spv[4] = {SP[j].x, SP[j].y, SP[j].z, SP[j].w};
            const float vv0[4] = {VPX[0].x, VPX[0].y, VPX[0].z, VPX[0].w};
            const float vv1[4] = {VPX[1].x, VPX[1].y, VPX[1].z, VPX[1].w};
            const float vv2[4] = {VPX[2].x, VPX[2].y, VPX[2].z, VPX[2].w};
            const float vv3[4] = {VPX[3].x, VPX[3].y, VPX[3].z, VPX[3].w};
            const float vv4[4] = {VPX[4].x, VPX[4].y, VPX[4].z, VPX[4].w};
            float r[4];
#pragma unroll
            for (int k = 0; k < 4; k++) {
                const float atv = p0 * vv0[k] + p1 * vv1[k] + p2 * vv2[k] +
                                  p3 * vv3[k] + p4 * vv4[k];
                r[k] = silu_f(atv * spv[k]);
            }
            float4 v4;
            v4.x = r[0]; v4.y = r[1]; v4.z = r[2]; v4.w = r[3];
            out4[j * 256 + t] = v4;
        }
        __syncthreads();   // protect spart/prob before next batch
    }
}

extern "C" void kernel_launch(void* const* d_in, const int* in_sizes, int n_in,
                              void* d_out, int out_size) {
    const float* values  = (const float*)d_in[0];
    const float* h       = (const float*)d_in[1];
    const float* symbols = (const float*)d_in[2];
    const float* gamma   = (const float*)d_in[3];
    const float* beta    = (const float*)d_in[4];
    float* out = (float*)d_out;

    const int B = in_sizes[0] / (NS * ND);

    sp_kernel<<<NS, 256>>>(h, symbols, gamma, beta);
    main_kernel<<<(B + 1) / 2, 256>>>(values, gamma, beta, out, B);
}

// round 7
// speedup vs baseline: 1.5570x; 1.0171x over previous
#include <cuda_runtime.h>

// Problem constants
#define NS 5
#define ND 64
#define NV 1024
#define NH 961
#define HPITCH 1092   // A copy: 63 zeros | 961 taps | 68 zeros (16B-aligned rows)
#define BPITCH 1088   // B copy: A shifted left by one float

// Precomputed once per launch:
__device__ float g_hp[NS][HPITCH];   // zero-padded taps
__device__ float g_hb[NS][BPITCH];   // g_hb[i] = g_hp[i+1]
__device__ float g_sp[NS][NV];       // sp = conv_net(symbols), batch-independent

__device__ __forceinline__ float silu_f(float y) {
    return y * (1.0f / (1.0f + __expf(-y)));
}

__device__ __forceinline__ float warp_sum(float v) {
#pragma unroll
    for (int o = 16; o; o >>= 1) v += __shfl_xor_sync(0xffffffffu, v, o);
    return v;
}

// packed dual-FMA: acc(lo,hi) += x(lo,hi) * g(lo,hi), elementwise fp32
__device__ __forceinline__ void ffma2(unsigned long long& acc,
                                      unsigned long long x,
                                      unsigned long long g) {
    asm("fma.rn.f32x2 %0, %1, %2, %0;" : "+l"(acc) : "l"(x), "l"(g));
}
__device__ __forceinline__ float u64lo(unsigned long long u) {
    return __uint_as_float((unsigned)u);
}
__device__ __forceinline__ float u64hi(unsigned long long u) {
    return __uint_as_float((unsigned)(u >> 32));
}

// ---- single-batch fully packed conv (used by sp_kernel only) ----
__device__ __forceinline__ void conv4p(const float* __restrict__ gA,
                                       const float* __restrict__ gB,
                                       const float* __restrict__ xs,
                                       float a[4]) {
    const ulonglong2* a2v = (const ulonglong2*)gA;
    const ulonglong2* b2v = (const ulonglong2*)gB;
    const ulonglong2* x2v = (const ulonglong2*)xs;
    unsigned long long A3 = 0ull, A2 = 0ull, A1 = 0ull, A0 = 0ull;
    ulonglong2 GA = a2v[0];
    ulonglong2 GB = b2v[0];
#pragma unroll
    for (int m = 0; m < 16; m++) {
        const ulonglong2 GAn = a2v[m + 1];
        const ulonglong2 GBn = b2v[m + 1];
        const ulonglong2 X = x2v[m];
        ffma2(A3, X.x, GA.x);
        ffma2(A1, X.x, GA.y);
        ffma2(A2, X.x, GB.x);
        ffma2(A0, X.x, GB.y);
        ffma2(A3, X.y, GA.y);
        ffma2(A1, X.y, GAn.x);
        ffma2(A2, X.y, GB.y);
        ffma2(A0, X.y, GBn.x);
        GA = GAn;
        GB = GBn;
    }
    a[3] = u64lo(A3) + u64hi(A3);
    a[2] = u64lo(A2) + u64hi(A2);
    a[1] = u64lo(A1) + u64hi(A1);
    a[0] = u64lo(A0) + u64hi(A0);
}

// --------------------------------------------------------------------------
// Kernel 1: pads h into g_hp + g_hb AND computes sp. 5 blocks, one per s.
// --------------------------------------------------------------------------
__global__ __launch_bounds__(256) void sp_kernel(
    const float* __restrict__ h, const float* __restrict__ symbols,
    const float* __restrict__ gamma, const float* __restrict__ beta) {
    __shared__ __align__(16) float hpA[HPITCH];
    __shared__ __align__(16) float hpB[BPITCH];
    __shared__ __align__(16) float xs[ND];
    __shared__ float wsum[8], wsq[8], mu_rs[2];
    const int s = blockIdx.x;
    const int t = threadIdx.x;
    const int warp = t >> 5, lane = t & 31;

    for (int i = t; i < HPITCH; i += 256) {
        const float v = (i >= 63 && i < 63 + NH) ? h[s * NH + (i - 63)] : 0.f;
        hpA[i] = v;
        g_hp[s][i] = v;
    }
    for (int i = t; i < BPITCH; i += 256) {
        const int j = i + 1;
        const float v = (j >= 63 && j < 63 + NH) ? h[s * NH + (j - 63)] : 0.f;
        hpB[i] = v;
        g_hb[s][i] = v;
    }
    if (t < ND) xs[t] = symbols[s * ND + t];
    __syncthreads();

    const int o0 = 4 * t;
    float a[4];
    conv4p(hpA + (1020 - o0), hpB + (1020 - o0), xs, a);

    float sm = 0.f, sq = 0.f;
#pragma unroll
    for (int k = 0; k < 4; k++) {
        a[k] = silu_f(a[k]);
        sm += a[k];
        sq += a[k] * a[k];
    }
    sm = warp_sum(sm);
    sq = warp_sum(sq);
    if (lane == 0) { wsum[warp] = sm; wsq[warp] = sq; }
    __syncthreads();
    if (t == 0) {
        float s1 = 0.f, s2 = 0.f;
#pragma unroll
        for (int w = 0; w < 8; w++) { s1 += wsum[w]; s2 += wsq[w]; }
        const float mu = s1 * (1.f / NV);
        mu_rs[0] = mu;
        mu_rs[1] = rsqrtf(s2 * (1.f / NV) - mu * mu + 1e-3f);
    }
    __syncthreads();
    const float mu = mu_rs[0], rstd = mu_rs[1];
#pragma unroll
    for (int k = 0; k < 4; k++) {
        const int o = o0 + k;
        g_sp[s][o] = (a[k] - mu) * rstd * gamma[o] + beta[o];
    }
}

// --------------------------------------------------------------------------
// Kernel 2: fused pipeline, TWO batches per CTA, 4 CTAs/SM.
// Dual-batch conv (window LDS amortized, 100% packed f32x2). Silu outputs
// are written into the tap rows that just died (hpA[s] row for batch 0,
// hpB[s] row for batch 1), so no bulk per-thread state survives the conv.
// LayerNorm is applied on the fly when the epilogue reads them back.
// --------------------------------------------------------------------------
__global__ __launch_bounds__(256, 4) void main_kernel(
    const float* __restrict__ values,
    const float* __restrict__ gamma, const float* __restrict__ beta,
    float* __restrict__ out, int B) {
    __shared__ __align__(16) float hpA[NS][HPITCH];   // taps; row s reused as sil(batch0)
    __shared__ __align__(16) float hpB[NS][BPITCH];   // taps; row s reused as sil(batch1)
    __shared__ __align__(16) float xs[2][NS][ND];
    __shared__ float wsum[2][NS][8], wsq[2][NS][8];
    __shared__ float mu_s[2][NS], rs_s[2][NS];
    __shared__ int   spart[25][8];
    __shared__ float prob[NS][NS];

    const int b0 = 2 * blockIdx.x;
    const int b1 = b0 + 1;
    const int t = threadIdx.x;
    const int warp = t >> 5, lane = t & 31;
    const int o0 = 4 * t;

    {   // taps + both batches' x (contiguous: b1 = b0+1)
        const float4* srcA = (const float4*)(&g_hp[0][0]);
        float4* dstA = (float4*)(&hpA[0][0]);
        for (int i = t; i < NS * HPITCH / 4; i += 256) dstA[i] = srcA[i];
        const float4* srcB = (const float4*)(&g_hb[0][0]);
        float4* dstB = (float4*)(&hpB[0][0]);
        for (int i = t; i < NS * BPITCH / 4; i += 256) dstB[i] = srcB[i];
        const float4* v4 = (const float4*)(values + (size_t)b0 * (NS * ND));
        const int nfl = (b1 < B) ? (2 * NS * ND / 4) : (NS * ND / 4);
        if (t < nfl) ((float4*)(&xs[0][0][0]))[t] = v4[t];
        else if (t < 2 * NS * ND / 4)
            ((float4*)(&xs[0][0][0]))[t] = make_float4(0.f, 0.f, 0.f, 0.f);
    }
    __syncthreads();

    // ---- conv (batch-innermost) + silu + LN partial sums, sil -> SMEM ----
#pragma unroll
    for (int s = 0; s < NS; s++) {
        const ulonglong2* a2v = (const ulonglong2*)(&hpA[s][1020 - o0]);
        const ulonglong2* b2v = (const ulonglong2*)(&hpB[s][1020 - o0]);
        const ulonglong2* x0 = (const ulonglong2*)(&xs[0][s][0]);
        const ulonglong2* x1 = (const ulonglong2*)(&xs[1][s][0]);
        unsigned long long P3 = 0ull, P2 = 0ull, P1 = 0ull, P0 = 0ull;
        unsigned long long Q3 = 0ull, Q2 = 0ull, Q1 = 0ull, Q0 = 0ull;
        ulonglong2 GA = a2v[0];
        ulonglong2 GB = b2v[0];
#pragma unroll
        for (int m = 0; m < 16; m++) {
            const ulonglong2 GAn = a2v[m + 1];
            const ulonglong2 GBn = b2v[m + 1];
            const ulonglong2 X = x0[m];
            const ulonglong2 Y = x1[m];
            ffma2(P3, X.x, GA.x);  ffma2(P1, X.x, GA.y);
            ffma2(P2, X.x, GB.x);  ffma2(P0, X.x, GB.y);
            ffma2(P3, X.y, GA.y);  ffma2(P1, X.y, GAn.x);
            ffma2(P2, X.y, GB.y);  ffma2(P0, X.y, GBn.x);
            ffma2(Q3, Y.x, GA.x);  ffma2(Q1, Y.x, GA.y);
            ffma2(Q2, Y.x, GB.x);  ffma2(Q0, Y.x, GB.y);
            ffma2(Q3, Y.y, GA.y);  ffma2(Q1, Y.y, GAn.x);
            ffma2(Q2, Y.y, GB.y);  ffma2(Q0, Y.y, GBn.x);
            GA = GAn;
            GB = GBn;
        }
        float a0[4], a1[4];
        a0[3] = u64lo(P3) + u64hi(P3); a0[2] = u64lo(P2) + u64hi(P2);
        a0[1] = u64lo(P1) + u64hi(P1); a0[0] = u64lo(P0) + u64hi(P0);
        a1[3] = u64lo(Q3) + u64hi(Q3); a1[2] = u64lo(Q2) + u64hi(Q2);
        a1[1] = u64lo(Q1) + u64hi(Q1); a1[0] = u64lo(Q0) + u64hi(Q0);

        float sm0 = 0.f, sq0 = 0.f, sm1 = 0.f, sq1 = 0.f;
#pragma unroll
        for (int k = 0; k < 4; k++) {
            a0[k] = silu_f(a0[k]);
            sm0 += a0[k]; sq0 += a0[k] * a0[k];
            a1[k] = silu_f(a1[k]);
            sm1 += a1[k]; sq1 += a1[k] * a1[k];
        }
        sm0 = warp_sum(sm0); sq0 = warp_sum(sq0);
        sm1 = warp_sum(sm1); sq1 = warp_sum(sq1);
        if (lane == 0) {
            wsum[0][s][warp] = sm0; wsq[0][s][warp] = sq0;
            wsum[1][s][warp] = sm1; wsq[1][s][warp] = sq1;
        }
        // rows hpA[s], hpB[s] are fully read by ALL warps before overwrite
        __syncthreads();
        ((float4*)(&hpA[s][0]))[t] = make_float4(a0[0], a0[1], a0[2], a0[3]);
        ((float4*)(&hpB[s][0]))[t] = make_float4(a1[0], a1[1], a1[2], a1[3]);
    }
    __syncthreads();
    if (t < 10) {
        const int bb = t / NS, ss = t % NS;
        float s1 = 0.f, s2 = 0.f;
#pragma unroll
        for (int w = 0; w < 8; w++) { s1 += wsum[bb][ss][w]; s2 += wsq[bb][ss][w]; }
        const float mu = s1 * (1.f / NV);
        mu_s[bb][ss] = mu;
        rs_s[bb][ss] = rsqrtf(s2 * (1.f / NV) - mu * mu + 1e-3f);
    }
    __syncthreads();

    // ---- epilogue, per batch sequentially; LN applied at read time ----
    const float4 gm4 = ((const float4*)gamma)[t];
    const float4 bt4 = ((const float4*)beta)[t];
    float4 SP[NS];
#pragma unroll
    for (int j = 0; j < NS; j++) SP[j] = ((const float4*)(&g_sp[j][0]))[t];

#pragma unroll
    for (int bb = 0; bb < 2; bb++) {
        if (bb == 1 && b1 >= B) break;

        float4 VPX[NS];
#pragma unroll
        for (int i = 0; i < NS; i++) {
            const float4 v = (bb == 0) ? ((const float4*)(&hpA[i][0]))[t]
                                       : ((const float4*)(&hpB[i][0]))[t];
            const float mu = mu_s[bb][i], rs = rs_s[bb][i];
            VPX[i].x = (v.x - mu) * rs * gm4.x + bt4.x;
            VPX[i].y = (v.y - mu) * rs * gm4.y + bt4.y;
            VPX[i].z = (v.z - mu) * rs * gm4.z + bt4.z;
            VPX[i].w = (v.w - mu) * rs * gm4.w + bt4.w;
        }

        // scores: sign(v)*sign(v+sp) = 1 - 2*(signbit xor); count flips.
        // Reduce per-j to keep only 5 live accumulators.
#pragma unroll
        for (int j = 0; j < NS; j++) {
            const float spv[4] = {SP[j].x, SP[j].y, SP[j].z, SP[j].w};
#pragma unroll
            for (int i = 0; i < NS; i++) {
                const float vv[4] = {VPX[i].x, VPX[i].y, VPX[i].z, VPX[i].w};
                int a = 0;
#pragma unroll
                for (int k = 0; k < 4; k++) {
                    const float c = vv[k] + spv[k];
                    a += (int)((__float_as_uint(vv[k]) ^
                                __float_as_uint(c)) >> 31);
                }
                const int v = __reduce_add_sync(0xffffffffu, a);
                if (lane == 0) spart[j * NS + i][warp] = v;
            }
        }
        __syncthreads();
        if (t < 25) {
            int sm = 0;
#pragma unroll
            for (int w = 0; w < 8; w++) sm += spart[t][w];
            ((float*)&spart[t][0])[0] = (float)(NV - 2 * sm) * (1.f / NV);
        }
        __syncthreads();
        if (t < NS) {
            float sc[NS], m = -1e30f;
#pragma unroll
            for (int i = 0; i < NS; i++) {
                sc[i] = ((float*)&spart[t * NS + i][0])[0];
                m = fmaxf(m, sc[i]);
            }
            float ssum = 0.f;
#pragma unroll
            for (int i = 0; i < NS; i++) { sc[i] = __expf(sc[i] - m); ssum += sc[i]; }
            const float inv = 1.f / ssum;
#pragma unroll
            for (int i = 0; i < NS; i++) prob[t][i] = sc[i] * inv;
        }
        __syncthreads();

        float4* out4 = (float4*)(out + (size_t)(b0 + bb) * (NS * NV));
#pragma unroll
        for (int j = 0; j < NS; j++) {
            const float p0 = prob[j][0], p1 = prob[j][1], p2 = prob[j][2],
                        p3 = prob[j][3], p4 = prob[j][4];
            const float spv[4] = {SP[j].x, SP[j].y, SP[j].z, SP[j].w};
            float r[4];
#pragma unroll
            for (int k = 0; k < 4; k++) {
                const float v0 = ((const float*)&VPX[0])[k];
                const float v1 = ((const float*)&VPX[1])[k];
                const float v2 = ((const float*)&VPX[2])[k];
                const float v3 = ((const float*)&VPX[3])[k];
                const float v4 = ((const float*)&VPX[4])[k];
                const float atv = p0 * v0 + p1 * v1 + p2 * v2 + p3 * v3 + p4 * v4;
                r[k] = silu_f(atv * spv[k]);
            }
            float4 w4;
            w4.x = r[0]; w4.y = r[1]; w4.z = r[2]; w4.w = r[3];
            out4[j * 256 + t] = w4;
        }
        __syncthreads();   // protect spart/prob before next batch
    }
}

extern "C" void kernel_launch(void* const* d_in, const int* in_sizes, int n_in,
                              void* d_out, int out_size) {
    const float* values  = (const float*)d_in[0];
    const float* h       = (const float*)d_in[1];
    const float* symbols = (const float*)d_in[2];
    const float* gamma   = (const float*)d_in[3];
    const float* beta    = (const float*)d_in[4];
    float* out = (float*)d_out;

    const int B = in_sizes[0] / (NS * ND);

    sp_kernel<<<NS, 256>>>(h, symbols, gamma, beta);
    main_kernel<<<(B + 1) / 2, 256>>>(values, gamma, beta, out, B);
}